// round 6
// baseline (speedup 1.0000x reference)
#include <cuda_runtime.h>
#include <cstdint>
#include <math.h>

#define BATCH 64
#define CH    512
#define NPIX  256
#define HEADS 8
#define HD    64

// Scratch (bf16 hi/lo stored as packed uint32 pairs) ------------------------
__device__ uint32_t g_wqh[1536 * 256], g_wql[1536 * 256];
__device__ uint32_t g_woh[512 * 256],  g_wol[512 * 256];
__device__ uint32_t g_xth[(size_t)BATCH * NPIX * 256], g_xtl[(size_t)BATCH * NPIX * 256];
__device__ uint32_t g_qh[(size_t)BATCH * 1536 * 128],  g_ql[(size_t)BATCH * 1536 * 128];
__device__ uint32_t g_ath[(size_t)BATCH * NPIX * 256], g_atl[(size_t)BATCH * NPIX * 256];

// ======================= helpers ==========================================
__device__ __forceinline__ uint32_t smem_to_u32(const void* p) {
    uint32_t a;
    asm("{ .reg .u64 t; cvta.to.shared.u64 t, %1; cvt.u32.u64 %0, t; }"
        : "=r"(a) : "l"(p));
    return a;
}
__device__ __forceinline__ uint32_t pack_bf16x2(float f_hi, float f_lo) {
    uint32_t r;
    asm("cvt.rn.bf16x2.f32 %0, %1, %2;" : "=r"(r) : "f"(f_hi), "f"(f_lo));
    return r;
}
__device__ __forceinline__ float bf_lo(uint32_t h) { return __uint_as_float(h << 16); }
__device__ __forceinline__ float bf_hi(uint32_t h) { return __uint_as_float(h & 0xFFFF0000u); }

__device__ __forceinline__ void ldm_x4(uint32_t* r, uint32_t addr) {
    asm volatile("ldmatrix.sync.aligned.m8n8.x4.shared.b16 {%0,%1,%2,%3}, [%4];"
        : "=r"(r[0]), "=r"(r[1]), "=r"(r[2]), "=r"(r[3]) : "r"(addr));
}
__device__ __forceinline__ void ldm_x4_t(uint32_t* r, uint32_t addr) {
    asm volatile("ldmatrix.sync.aligned.m8n8.x4.trans.shared.b16 {%0,%1,%2,%3}, [%4];"
        : "=r"(r[0]), "=r"(r[1]), "=r"(r[2]), "=r"(r[3]) : "r"(addr));
}
__device__ __forceinline__ void mma_bf16(float* c, const uint32_t* a,
                                         const uint32_t* b) {
    asm volatile(
        "mma.sync.aligned.m16n8k16.row.col.f32.bf16.bf16.f32 "
        "{%0,%1,%2,%3}, {%4,%5,%6,%7}, {%8,%9}, {%0,%1,%2,%3};"
        : "+f"(c[0]), "+f"(c[1]), "+f"(c[2]), "+f"(c[3])
        : "r"(a[0]), "r"(a[1]), "r"(a[2]), "r"(a[3]), "r"(b[0]), "r"(b[1]));
}

#define CP16(smem, gptr) \
    asm volatile("cp.async.ca.shared.global [%0], [%1], 16;" \
        :: "r"((uint32_t)(smem)), "l"(gptr) : "memory")
#define CP_COMMIT() asm volatile("cp.async.commit_group;" ::: "memory")
#define CP_WAIT(n)  asm volatile("cp.async.wait_group %0;" :: "n"(n) : "memory")

// exp via FMA pipe, |relerr|<3e-6
__device__ __forceinline__ float fast_exp(float t) {
    float y = t * 1.4426950408889634f;
    y = fmaxf(y, -126.0f);
    int ni = __float2int_rn(y);
    float f = y - (float)ni;
    float p = 1.3333558146428443e-3f;
    p = fmaf(p, f, 9.618129842071803e-3f);
    p = fmaf(p, f, 5.550410866482158e-2f);
    p = fmaf(p, f, 2.402265069591007e-1f);
    p = fmaf(p, f, 6.931471805599453e-1f);
    p = fmaf(p, f, 1.0f);
    return __uint_as_float(__float_as_uint(p) + ((uint32_t)ni << 23));
}

// ---------------------------------------------------------------------------
// Preconvert kernels
// ---------------------------------------------------------------------------
__global__ void convert_w(const float* __restrict__ w, uint32_t* __restrict__ wh,
                          uint32_t* __restrict__ wl, int n) {
    int i = blockIdx.x * 256 + threadIdx.x;
    if (i < n) {
        float2 v = ((const float2*)w)[i];
        uint32_t h = pack_bf16x2(v.y, v.x);
        uint32_t l = pack_bf16x2(v.y - bf_hi(h), v.x - bf_lo(h));
        wh[i] = h;
        wl[i] = l;
    }
}

// x [b][c][p] fp32 -> Xt hi/lo [b][p][c] bf16 (packed c-pairs)
__global__ __launch_bounds__(256) void convert_x(const float* __restrict__ x,
                                                 uint32_t* __restrict__ xh,
                                                 uint32_t* __restrict__ xl) {
    __shared__ float t[32][33];
    const int b = blockIdx.z, c0 = blockIdx.y * 32, p0 = blockIdx.x * 32;
    const int tx = threadIdx.x & 31, ty = threadIdx.x >> 5;
    const float* xp = x + ((size_t)b * CH + c0 + ty) * NPIX + p0 + tx;
    #pragma unroll
    for (int i = 0; i < 32; i += 8) t[ty + i][tx] = xp[(size_t)i * NPIX];
    __syncthreads();
    const int p = threadIdx.x >> 3, j0 = threadIdx.x & 7;
    const size_t base = ((size_t)b * NPIX + p0 + p) * (CH / 2) + c0 / 2;
    #pragma unroll
    for (int jj = 0; jj < 2; jj++) {
        int j = j0 + jj * 8;
        float v0 = t[2 * j][p], v1 = t[2 * j + 1][p];
        uint32_t h = pack_bf16x2(v1, v0);
        uint32_t l = pack_bf16x2(v1 - bf_hi(h), v0 - bf_lo(h));
        xh[base + j] = h;
        xl[base + j] = l;
    }
}

// ---------------------------------------------------------------------------
// GEMM: Y[b][o][p] = sum_c W[o][c] X[b][c][p] + bias[o]
// CTA 128x128, 4 warps (2x2), warp tile 64x64 -> 9.2x LDSM reuse.
// 3-stage cp.async pipeline, k32 per stage, XOR-swizzled 64B rows (no pad).
// ---------------------------------------------------------------------------
#define RG_AH 0
#define RG_AL 8192
#define RG_BH 16384
#define RG_BL 24576
#define STAGE 32768
#define GSMEM (3 * STAGE)

template <int M, bool PACK>
__global__ __launch_bounds__(128, 2) void gemm_v6(
    const uint32_t* __restrict__ Ah, const uint32_t* __restrict__ Al,
    const uint32_t* __restrict__ Bh, const uint32_t* __restrict__ Bl,
    const float* __restrict__ bias,
    float* __restrict__ Yf, uint32_t* __restrict__ Yh, uint32_t* __restrict__ Yl)
{
    extern __shared__ char smem[];
    const uint32_t sb = smem_to_u32(smem);
    const int tid = threadIdx.x, lane = tid & 31, wid = tid >> 5;
    const int wm = wid >> 1, wn = wid & 1;
    const int p0 = blockIdx.x * 128, m0 = blockIdx.y * 128, b = blockIdx.z;

    // ---- cp.async: thread -> one row (128 rows per region), 4 chunks ------
    const char* gA_h = (const char*)Ah + (size_t)(m0 + tid) * 1024;
    const char* gA_l = (const char*)Al + (size_t)(m0 + tid) * 1024;
    const char* gB_h = (const char*)Bh + (size_t)(b * NPIX + p0 + tid) * 1024;
    const char* gB_l = (const char*)Bl + (size_t)(b * NPIX + p0 + tid) * 1024;
    const uint32_t swc = (tid >> 1) & 3;                 // row swizzle
    const uint32_t srow = sb + (uint32_t)tid * 64;

    auto issue = [&](int s, int slot) {
        if (s < 16) {
            const uint32_t sd = srow + slot * STAGE;
            const size_t go = (size_t)s * 64;
            #pragma unroll
            for (int c = 0; c < 4; c++) {
                const uint32_t so = ((uint32_t)c ^ swc) * 16;
                const size_t gc = go + c * 16;
                CP16(sd + RG_AH + so, gA_h + gc);
                CP16(sd + RG_AL + so, gA_l + gc);
                CP16(sd + RG_BH + so, gB_h + gc);
                CP16(sd + RG_BL + so, gB_l + gc);
            }
        }
        CP_COMMIT();
    };

    float acc[4][8][4];
    #pragma unroll
    for (int mi = 0; mi < 4; mi++)
        #pragma unroll
        for (int nj = 0; nj < 8; nj++)
            #pragma unroll
            for (int e = 0; e < 4; e++) acc[mi][nj][e] = 0.f;

    // ---- LDSM lane addressing (swizzle folds to lane-constant XOR) --------
    const uint32_t arow = (uint32_t)(wm * 64 + (lane & 15));
    const uint32_t ah_bit = (lane >> 4) & 1;             // k-half within k16
    const uint32_t aswz = ((lane & 15) >> 1) & 3;
    const uint32_t brow = (uint32_t)(wn * 64 + ((lane >> 4) & 1) * 8 + (lane & 7));
    const uint32_t bh_bit = (lane >> 3) & 1;
    const uint32_t bswz = ((lane & 7) >> 1) & 3;

    issue(0, 0);
    issue(1, 1);

    #pragma unroll 1
    for (int c = 0; c < 16; c++) {
        CP_WAIT(1);
        __syncthreads();
        issue(c + 2, (c + 2) % 3);

        const uint32_t stb = sb + (c % 3) * STAGE;
        #pragma unroll
        for (int ks = 0; ks < 2; ks++) {
            const uint32_t achunk = (((uint32_t)(ks << 1) | ah_bit) ^ aswz) * 16;
            const uint32_t bchunk = (((uint32_t)(ks << 1) | bh_bit) ^ bswz) * 16;
            uint32_t ah[4][4], al[4][4], bh[4][4], bl[4][4];
            #pragma unroll
            for (int mi = 0; mi < 4; mi++) {
                const uint32_t ra = stb + (arow + mi * 16) * 64 + achunk;
                ldm_x4(ah[mi], ra + RG_AH);
                ldm_x4(al[mi], ra + RG_AL);
            }
            #pragma unroll
            for (int p = 0; p < 4; p++) {
                const uint32_t rb = stb + (brow + p * 16) * 64 + bchunk;
                ldm_x4(bh[p], rb + RG_BH);
                ldm_x4(bl[p], rb + RG_BL);
            }
            #pragma unroll
            for (int mi = 0; mi < 4; mi++)
                #pragma unroll
                for (int nj = 0; nj < 8; nj++) {
                    const uint32_t* bhp = &bh[nj >> 1][(nj & 1) * 2];
                    const uint32_t* blp = &bl[nj >> 1][(nj & 1) * 2];
                    mma_bf16(acc[mi][nj], ah[mi], bhp);
                    mma_bf16(acc[mi][nj], ah[mi], blp);
                    mma_bf16(acc[mi][nj], al[mi], bhp);
                }
        }
    }

    // ---- epilogue ----
    #pragma unroll
    for (int mi = 0; mi < 4; mi++) {
        const int rr = wm * 64 + mi * 16 + (lane >> 2);
        const float bv0 = __ldg(&bias[m0 + rr]);
        const float bv1 = __ldg(&bias[m0 + rr + 8]);
        if (PACK) {
            size_t r0 = ((size_t)b * M + m0 + rr) * 128 + (p0 >> 1) + wn * 32 + (lane & 3);
            size_t r1 = r0 + 8 * 128;
            #pragma unroll
            for (int nj = 0; nj < 8; nj++) {
                float v0 = acc[mi][nj][0] + bv0, v1 = acc[mi][nj][1] + bv0;
                uint32_t h = pack_bf16x2(v1, v0);
                uint32_t l = pack_bf16x2(v1 - bf_hi(h), v0 - bf_lo(h));
                Yh[r0 + nj * 4] = h;
                Yl[r0 + nj * 4] = l;
                float w0 = acc[mi][nj][2] + bv1, w1 = acc[mi][nj][3] + bv1;
                uint32_t h2 = pack_bf16x2(w1, w0);
                uint32_t l2 = pack_bf16x2(w1 - bf_hi(h2), w0 - bf_lo(h2));
                Yh[r1 + nj * 4] = h2;
                Yl[r1 + nj * 4] = l2;
            }
        } else {
            float* y0 = Yf + ((size_t)b * M + m0 + rr) * NPIX + p0 + wn * 64 + (lane & 3) * 2;
            float* y1 = y0 + 8 * NPIX;
            #pragma unroll
            for (int nj = 0; nj < 8; nj++) {
                *(float2*)(y0 + nj * 8) =
                    make_float2(acc[mi][nj][0] + bv0, acc[mi][nj][1] + bv0);
                *(float2*)(y1 + nj * 8) =
                    make_float2(acc[mi][nj][2] + bv1, acc[mi][nj][3] + bv1);
            }
        }
    }
}

// ---------------------------------------------------------------------------
// Attention on tensor cores (unchanged from R5; bf16 hi/lo in, transposed
// bf16 hi/lo out for the out-projection).
// ---------------------------------------------------------------------------
#define AT_QH   0
#define AT_QL   9216
#define AT_KH   18432
#define AT_KL   52224
#define AT_VH   86016
#define AT_VL   119808
#define AT_REL  153600
#define AT_MAXB 157456
#define AT_SUMB 157968
#define AT_RS   158480
#define AT_SMEM 158736

__global__ __launch_bounds__(256, 1) void attn_mma(
    const float* __restrict__ rel,
    const uint32_t* __restrict__ qkvh, const uint32_t* __restrict__ qkvl,
    uint32_t* __restrict__ ath, uint32_t* __restrict__ atl)
{
    extern __shared__ char sm[];
    float* smf = (float*)sm;
    const uint32_t sb = smem_to_u32(sm);

    const int tid  = threadIdx.x;
    const int lane = tid & 31;
    const int wid  = tid >> 5;
    const int wn   = wid & 3;
    const int wm   = wid >> 2;
    const int n0g  = blockIdx.x * 64;
    const int h    = blockIdx.y;
    const int b    = blockIdx.z;

    const char* qh = (const char*)(qkvh + ((size_t)b * 1536 + h * 64) * 128);
    const char* ql = (const char*)(qkvl + ((size_t)b * 1536 + h * 64) * 128);
    const char* kh = qh + (size_t)CH * 512;
    const char* kl = ql + (size_t)CH * 512;
    const char* vh = qh + (size_t)2 * CH * 512;
    const char* vl = ql + (size_t)2 * CH * 512;

    #pragma unroll
    for (int it = 0; it < 2; it++) {
        int i = tid + it * 256;
        int d = i >> 3, ch = i & 7;
        CP16(sb + AT_QH + d * 144 + ch * 16, qh + d * 512 + n0g * 2 + ch * 16);
        CP16(sb + AT_QL + d * 144 + ch * 16, ql + d * 512 + n0g * 2 + ch * 16);
    }
    #pragma unroll
    for (int it = 0; it < 8; it++) {
        int i = tid + it * 256;
        int d = i >> 5, ch = i & 31;
        CP16(sb + AT_KH + d * 528 + ch * 16, kh + d * 512 + ch * 16);
        CP16(sb + AT_KL + d * 528 + ch * 16, kl + d * 512 + ch * 16);
        CP16(sb + AT_VH + d * 528 + ch * 16, vh + d * 512 + ch * 16);
        CP16(sb + AT_VL + d * 528 + ch * 16, vl + d * 512 + ch * 16);
    }
    CP_COMMIT();
    for (int i = tid; i < 961; i += 256)
        smf[AT_REL / 4 + i] = rel[h * 961 + i];
    CP_WAIT(0);
    __syncthreads();

    // ---- S = Q^T K (3-term split) ------------------------------------------
    float acc[16][4];
    #pragma unroll
    for (int f = 0; f < 16; f++)
        #pragma unroll
        for (int e = 0; e < 4; e++) acc[f][e] = 0.f;

    const uint32_t a_row = ((lane >> 4) & 1) * 8 + (lane & 7);
    const uint32_t a_col = (uint32_t)(wn * 16 + ((lane >> 3) & 1) * 8) * 2;
    const uint32_t b_row = ((lane >> 3) & 1) * 8 + (lane & 7);
    const uint32_t b_col8 = ((lane >> 4) & 1) * 8;

    #pragma unroll
    for (int s = 0; s < 4; s++) {
        uint32_t ah[4], al[4];
        ldm_x4_t(ah, sb + AT_QH + (s * 16 + a_row) * 144 + a_col);
        ldm_x4_t(al, sb + AT_QL + (s * 16 + a_row) * 144 + a_col);
        #pragma unroll
        for (int mg = 0; mg < 8; mg++) {
            const uint32_t mcol = (uint32_t)(wm * 128 + mg * 16 + b_col8) * 2;
            uint32_t bh[4], bl[4];
            ldm_x4_t(bh, sb + AT_KH + (s * 16 + b_row) * 528 + mcol);
            ldm_x4_t(bl, sb + AT_KL + (s * 16 + b_row) * 528 + mcol);
            mma_bf16(acc[2 * mg], ah, &bh[0]);
            mma_bf16(acc[2 * mg], ah, &bl[0]);
            mma_bf16(acc[2 * mg], al, &bh[0]);
            mma_bf16(acc[2 * mg + 1], ah, &bh[2]);
            mma_bf16(acc[2 * mg + 1], ah, &bl[2]);
            mma_bf16(acc[2 * mg + 1], al, &bh[2]);
        }
    }

    const int rq  = lane >> 2;
    const int nr  = n0g + wn * 16 + rq;
    const int nr8 = nr + 8;
    const int nb0 = (nr >> 4) * 31 + (nr & 15) + 480;
    const int nb8 = (nr8 >> 4) * 31 + (nr8 & 15) + 480;
    const float* Rs = smf + AT_REL / 4;

    float mx0 = -1e30f, mx8 = -1e30f;
    #pragma unroll
    for (int f = 0; f < 16; f++) {
        int mc = wm * 128 + f * 8 + (lane & 3) * 2;
        int mi0 = (mc >> 4) * 31 + (mc & 15);
        int mi1 = ((mc + 1) >> 4) * 31 + ((mc + 1) & 15);
        acc[f][0] = fmaf(acc[f][0], 0.125f, Rs[nb0 - mi0]);
        acc[f][1] = fmaf(acc[f][1], 0.125f, Rs[nb0 - mi1]);
        acc[f][2] = fmaf(acc[f][2], 0.125f, Rs[nb8 - mi0]);
        acc[f][3] = fmaf(acc[f][3], 0.125f, Rs[nb8 - mi1]);
        mx0 = fmaxf(mx0, fmaxf(acc[f][0], acc[f][1]));
        mx8 = fmaxf(mx8, fmaxf(acc[f][2], acc[f][3]));
    }
    mx0 = fmaxf(mx0, __shfl_xor_sync(0xFFFFFFFF, mx0, 1));
    mx0 = fmaxf(mx0, __shfl_xor_sync(0xFFFFFFFF, mx0, 2));
    mx8 = fmaxf(mx8, __shfl_xor_sync(0xFFFFFFFF, mx8, 1));
    mx8 = fmaxf(mx8, __shfl_xor_sync(0xFFFFFFFF, mx8, 2));
    float* maxb = smf + AT_MAXB / 4;
    const int row = wn * 16 + rq;
    if ((lane & 3) == 0) {
        maxb[wm * 64 + row]     = mx0;
        maxb[wm * 64 + row + 8] = mx8;
    }
    __syncthreads();
    mx0 = fmaxf(maxb[row],     maxb[64 + row]);
    mx8 = fmaxf(maxb[row + 8], maxb[64 + row + 8]);

    float s0 = 0.f, s8 = 0.f;
    #pragma unroll
    for (int f = 0; f < 16; f++) {
        acc[f][0] = fast_exp(acc[f][0] - mx0);
        acc[f][1] = fast_exp(acc[f][1] - mx0);
        acc[f][2] = fast_exp(acc[f][2] - mx8);
        acc[f][3] = fast_exp(acc[f][3] - mx8);
        s0 += acc[f][0] + acc[f][1];
        s8 += acc[f][2] + acc[f][3];
    }
    s0 += __shfl_xor_sync(0xFFFFFFFF, s0, 1);
    s0 += __shfl_xor_sync(0xFFFFFFFF, s0, 2);
    s8 += __shfl_xor_sync(0xFFFFFFFF, s8, 1);
    s8 += __shfl_xor_sync(0xFFFFFFFF, s8, 2);
    float* sumb = smf + AT_SUMB / 4;
    if ((lane & 3) == 0) {
        sumb[wm * 64 + row]     = s0;
        sumb[wm * 64 + row + 8] = s8;
    }
    __syncthreads();
    if (wm == 0 && (lane & 3) == 0) {
        smf[AT_RS / 4 + row]     = 1.f / (sumb[row] + sumb[64 + row]);
        smf[AT_RS / 4 + row + 8] = 1.f / (sumb[row + 8] + sumb[64 + row + 8]);
    }

    uint32_t ph[16][2], pl[16][2];
    #pragma unroll
    for (int f = 0; f < 16; f++) {
        uint32_t h01 = pack_bf16x2(acc[f][1], acc[f][0]);
        uint32_t h23 = pack_bf16x2(acc[f][3], acc[f][2]);
        pl[f][0] = pack_bf16x2(acc[f][1] - bf_hi(h01), acc[f][0] - bf_lo(h01));
        pl[f][1] = pack_bf16x2(acc[f][3] - bf_hi(h23), acc[f][2] - bf_lo(h23));
        ph[f][0] = h01;
        ph[f][1] = h23;
    }

    float oacc[8][4];
    #pragma unroll
    for (int g = 0; g < 8; g++)
        #pragma unroll
        for (int e = 0; e < 4; e++) oacc[g][e] = 0.f;

    const uint32_t v_row = ((lane >> 4) & 1) * 8 + (lane & 7);
    const uint32_t v_colh = ((lane >> 3) & 1) * 16;

    #pragma unroll
    for (int s = 0; s < 8; s++) {
        uint32_t a_h[4] = {ph[2 * s][0], ph[2 * s][1], ph[2 * s + 1][0], ph[2 * s + 1][1]};
        uint32_t a_l[4] = {pl[2 * s][0], pl[2 * s][1], pl[2 * s + 1][0], pl[2 * s + 1][1]};
        const uint32_t vcol = (uint32_t)(wm * 128 + s * 16) * 2 + v_colh;
        #pragma unroll
        for (int dg = 0; dg < 4; dg++) {
            uint32_t bh[4], bl[4];
            const uint32_t vaddr = (dg * 16 + v_row) * 528 + vcol;
            ldm_x4(bh, sb + AT_VH + vaddr);
            ldm_x4(bl, sb + AT_VL + vaddr);
            mma_bf16(oacc[2 * dg], a_h, &bh[0]);
            mma_bf16(oacc[2 * dg], a_h, &bl[0]);
            mma_bf16(oacc[2 * dg], a_l, &bh[0]);
            mma_bf16(oacc[2 * dg + 1], a_h, &bh[2]);
            mma_bf16(oacc[2 * dg + 1], a_h, &bl[2]);
            mma_bf16(oacc[2 * dg + 1], a_l, &bh[2]);
        }
    }

    float* Osm = smf + AT_KH / 4;              // [2][64][68]
    #pragma unroll
    for (int g = 0; g < 8; g++) {
        int d = g * 8 + (lane & 3) * 2;
        float* q0 = Osm + (wm * 64 + d) * 68 + row;
        float* q1 = Osm + (wm * 64 + d + 1) * 68 + row;
        q0[0] = oacc[g][0];
        q1[0] = oacc[g][1];
        q0[8] = oacc[g][2];
        q1[8] = oacc[g][3];
    }
    __syncthreads();

    {
        const int n  = tid >> 2;
        const int dq = tid & 3;
        const float rsv = smf[AT_RS / 4 + n];
        const size_t obase = ((size_t)b * NPIX + n0g + n) * 256 + h * 32 + dq * 8;
        #pragma unroll
        for (int j = 0; j < 8; j++) {
            int d0 = dq * 16 + 2 * j;
            float o0 = (Osm[d0 * 68 + n] + Osm[(64 + d0) * 68 + n]) * rsv;
            float o1 = (Osm[(d0 + 1) * 68 + n] + Osm[(64 + d0 + 1) * 68 + n]) * rsv;
            uint32_t hh = pack_bf16x2(o1, o0);
            uint32_t ll = pack_bf16x2(o1 - bf_hi(hh), o0 - bf_lo(hh));
            ath[obase + j] = hh;
            atl[obase + j] = ll;
        }
    }
}

// ---------------------------------------------------------------------------
extern "C" void kernel_launch(void* const* d_in, const int* in_sizes, int n_in,
                              void* d_out, int out_size)
{
    const float* x      = (const float*)d_in[0];
    const float* qkv_w  = (const float*)d_in[1];
    const float* qkv_b  = (const float*)d_in[2];
    const float* out_w  = (const float*)d_in[3];
    const float* out_b  = (const float*)d_in[4];
    const float* rel    = (const float*)d_in[5];
    float* out = (float*)d_out;

    void *wqh, *wql, *woh, *wol, *xth, *xtl, *qh, *ql, *ath, *atl;
    cudaGetSymbolAddress(&wqh, g_wqh);  cudaGetSymbolAddress(&wql, g_wql);
    cudaGetSymbolAddress(&woh, g_woh);  cudaGetSymbolAddress(&wol, g_wol);
    cudaGetSymbolAddress(&xth, g_xth);  cudaGetSymbolAddress(&xtl, g_xtl);
    cudaGetSymbolAddress(&qh,  g_qh);   cudaGetSymbolAddress(&ql,  g_ql);
    cudaGetSymbolAddress(&ath, g_ath);  cudaGetSymbolAddress(&atl, g_atl);

    cudaFuncSetAttribute(gemm_v6<3 * CH, true>,
                         cudaFuncAttributeMaxDynamicSharedMemorySize, GSMEM);
    cudaFuncSetAttribute(gemm_v6<CH, false>,
                         cudaFuncAttributeMaxDynamicSharedMemorySize, GSMEM);
    cudaFuncSetAttribute(attn_mma,
                         cudaFuncAttributeMaxDynamicSharedMemorySize, AT_SMEM);

    // 0) preconvert weights + transposed activations to bf16 hi/lo
    convert_w<<<(1536 * 256) / 256, 256>>>(qkv_w, (uint32_t*)wqh, (uint32_t*)wql,
                                           1536 * 256);
    convert_w<<<(512 * 256) / 256, 256>>>(out_w, (uint32_t*)woh, (uint32_t*)wol,
                                          512 * 256);
    convert_x<<<dim3(NPIX / 32, CH / 32, BATCH), 256>>>(x, (uint32_t*)xth,
                                                        (uint32_t*)xtl);

    // 1) QKV projection -> packed bf16 hi/lo (+bias)
    gemm_v6<3 * CH, true><<<dim3(NPIX / 128, 1536 / 128, BATCH), 128, GSMEM>>>(
        (const uint32_t*)wqh, (const uint32_t*)wql,
        (const uint32_t*)xth, (const uint32_t*)xtl,
        qkv_b, nullptr, (uint32_t*)qh, (uint32_t*)ql);

    // 2) Attention -> transposed packed bf16 hi/lo
    attn_mma<<<dim3(NPIX / 64, HEADS, BATCH), 256, AT_SMEM>>>(
        rel, (const uint32_t*)qh, (const uint32_t*)ql,
        (uint32_t*)ath, (uint32_t*)atl);

    // 3) Output projection -> fp32 out (+bias)
    gemm_v6<CH, false><<<dim3(NPIX / 128, CH / 128, BATCH), 128, GSMEM>>>(
        (const uint32_t*)woh, (const uint32_t*)wol,
        (const uint32_t*)ath, (const uint32_t*)atl,
        out_b, out, nullptr, nullptr);
}

// round 7
// speedup vs baseline: 1.7658x; 1.7658x over previous
#include <cuda_runtime.h>
#include <cuda_fp16.h>
#include <cstdint>
#include <math.h>

#define BATCH 64
#define CH    512
#define NPIX  256
#define HEADS 8
#define HD    64

// Scratch (no cudaMalloc allowed) -----------------------------------------
__device__ float g_qkv[(size_t)BATCH * 3 * CH * NPIX];  // [b][o][p]
__device__ float g_att[(size_t)BATCH * CH * NPIX];      // [b][c][p]

// ======================= helpers ==========================================
__device__ __forceinline__ uint32_t smem_to_u32(const void* p) {
    uint32_t a;
    asm("{ .reg .u64 t; cvta.to.shared.u64 t, %1; cvt.u32.u64 %0, t; }"
        : "=r"(a) : "l"(p));
    return a;
}
__device__ __forceinline__ uint32_t h2u(__half2 h) {
    return *reinterpret_cast<uint32_t*>(&h);
}
// fp16 convert (single-rounded) of 4 floats -> 2 packed half2
__device__ __forceinline__ void cvt4_f16(char* dst, float4 v) {
    __half2 a = __floats2half2_rn(v.x, v.y);
    __half2 b = __floats2half2_rn(v.z, v.w);
    *(uint2*)dst = make_uint2(h2u(a), h2u(b));
}
// fp16 2-term split (hi + residual) of 4 floats
__device__ __forceinline__ void split4_f16(char* hdst, char* ldst, float4 v) {
    __half2 a = __floats2half2_rn(v.x, v.y);
    __half2 b = __floats2half2_rn(v.z, v.w);
    float2 fa = __half22float2(a), fb = __half22float2(b);
    __half2 ra = __floats2half2_rn(v.x - fa.x, v.y - fa.y);
    __half2 rb = __floats2half2_rn(v.z - fb.x, v.w - fb.y);
    *(uint2*)hdst = make_uint2(h2u(a), h2u(b));
    *(uint2*)ldst = make_uint2(h2u(ra), h2u(rb));
}

__device__ __forceinline__ void ldm_x4(uint32_t* r, uint32_t addr) {
    asm volatile("ldmatrix.sync.aligned.m8n8.x4.shared.b16 {%0,%1,%2,%3}, [%4];"
        : "=r"(r[0]), "=r"(r[1]), "=r"(r[2]), "=r"(r[3]) : "r"(addr));
}
__device__ __forceinline__ void ldm_x4_t(uint32_t* r, uint32_t addr) {
    asm volatile("ldmatrix.sync.aligned.m8n8.x4.trans.shared.b16 {%0,%1,%2,%3}, [%4];"
        : "=r"(r[0]), "=r"(r[1]), "=r"(r[2]), "=r"(r[3]) : "r"(addr));
}
__device__ __forceinline__ void mma_f16(float* c, const uint32_t* a,
                                        const uint32_t* b) {
    asm volatile(
        "mma.sync.aligned.m16n8k16.row.col.f32.f16.f16.f32 "
        "{%0,%1,%2,%3}, {%4,%5,%6,%7}, {%8,%9}, {%0,%1,%2,%3};"
        : "+f"(c[0]), "+f"(c[1]), "+f"(c[2]), "+f"(c[3])
        : "r"(a[0]), "r"(a[1]), "r"(a[2]), "r"(a[3]), "r"(b[0]), "r"(b[1]));
}

// exp via FMA pipe, |relerr|<3e-6
__device__ __forceinline__ float fast_exp(float t) {
    float y = t * 1.4426950408889634f;
    y = fmaxf(y, -126.0f);
    int ni = __float2int_rn(y);
    float f = y - (float)ni;
    float p = 1.3333558146428443e-3f;
    p = fmaf(p, f, 9.618129842071803e-3f);
    p = fmaf(p, f, 5.550410866482158e-2f);
    p = fmaf(p, f, 2.402265069591007e-1f);
    p = fmaf(p, f, 6.931471805599453e-1f);
    p = fmaf(p, f, 1.0f);
    return __uint_as_float(__float_as_uint(p) + ((uint32_t)ni << 23));
}

// ---------------------------------------------------------------------------
// GEMM via mma.sync fp16 (A 2-term split, B single-rounded; 2 MMAs/term):
//   Y[b][o][p] = sum_c W[o][c] * X[b][c][p] + bias[o]
// CTA 64x64, 128 threads = 4 warps (2x2), warp tile 32x32, k-chunks of 32.
// ---------------------------------------------------------------------------
#define A_HI 0
#define A_LO 5120
#define B_HI 10240
#define GEMM_SMEM_BYTES 15360

template <int M>
__global__ __launch_bounds__(128, 1) void gemm_mma(
    const float* __restrict__ W, const float* __restrict__ X,
    const float* __restrict__ bias, float* __restrict__ Y)
{
    __shared__ __align__(128) char smem[GEMM_SMEM_BYTES];
    const uint32_t sb = smem_to_u32(smem);

    const int tid = threadIdx.x;
    const int wid = tid >> 5;
    const int lid = tid & 31;
    const int wm = wid >> 1;
    const int wn = wid & 1;
    const int p0 = blockIdx.x * 64;
    const int m0 = blockIdx.y * 64;
    const int b  = blockIdx.z;

    const int am  = tid >> 3;
    const int akq = tid & 7;
    const float* wp = W + (size_t)(m0 + am) * CH + akq * 4;
    const int bn = tid & 63;
    const int bg = tid >> 6;
    const float* xp = X + (size_t)b * CH * NPIX + p0 + bn;

    const uint32_t aoff = (uint32_t)(wm * 32 + (lid & 15)) * 80 + (lid >> 4) * 16;
    const uint32_t aAH0 = sb + A_HI + aoff;
    const uint32_t aAL0 = sb + A_LO + aoff;
    const int q = lid >> 3;
    const uint32_t boff =
        (uint32_t)(wn * 32 + ((q >> 1) & 1) * 8 + (lid & 7)) * 80 + (q & 1) * 16;
    const uint32_t aBH0 = sb + B_HI + boff;

    float acc[2][4][4];
    #pragma unroll
    for (int mi = 0; mi < 2; mi++)
        #pragma unroll
        for (int nj = 0; nj < 4; nj++)
            #pragma unroll
            for (int e = 0; e < 4; e++) acc[mi][nj][e] = 0.f;

    float4 ra[4];
    float  rb[16];
    #pragma unroll
    for (int i = 0; i < 4; i++)
        ra[i] = *(const float4*)(wp + (size_t)(16 * i) * CH);
    #pragma unroll
    for (int j = 0; j < 16; j++)
        rb[j] = xp[(size_t)(bg * 16 + j) * NPIX];

    #pragma unroll 1
    for (int c = 0; c < 16; c++) {
        // ---- STS current chunk ----
        #pragma unroll
        for (int i = 0; i < 4; i++) {
            uint32_t off = (uint32_t)(am + 16 * i) * 80 + akq * 8;
            split4_f16(smem + A_HI + off, smem + A_LO + off, ra[i]);
        }
        {
            uint32_t base = (uint32_t)bn * 80 + bg * 32;
            #pragma unroll
            for (int qq = 0; qq < 4; qq++) {
                float4 v = make_float4(rb[qq * 4 + 0], rb[qq * 4 + 1],
                                       rb[qq * 4 + 2], rb[qq * 4 + 3]);
                cvt4_f16(smem + B_HI + base + qq * 8, v);
            }
        }
        __syncthreads();

        if (c < 15) {
            const int k0 = (c + 1) * 32;
            #pragma unroll
            for (int i = 0; i < 4; i++)
                ra[i] = *(const float4*)(wp + (size_t)(16 * i) * CH + k0);
            #pragma unroll
            for (int j = 0; j < 16; j++)
                rb[j] = xp[(size_t)(k0 + bg * 16 + j) * NPIX];
        }

        #pragma unroll
        for (int ks = 0; ks < 2; ks++) {
            const uint32_t kb = ks * 32;
            uint32_t ah[2][4], al[2][4], bh[2][4];
            ldm_x4(ah[0], aAH0 + kb);
            ldm_x4(ah[1], aAH0 + 16 * 80 + kb);
            ldm_x4(al[0], aAL0 + kb);
            ldm_x4(al[1], aAL0 + 16 * 80 + kb);
            ldm_x4(bh[0], aBH0 + kb);
            ldm_x4(bh[1], aBH0 + 16 * 80 + kb);

            #pragma unroll
            for (int mi = 0; mi < 2; mi++)
                #pragma unroll
                for (int nj = 0; nj < 4; nj++) {
                    const uint32_t* bhp = &bh[nj >> 1][(nj & 1) * 2];
                    mma_f16(acc[mi][nj], ah[mi], bhp);
                    mma_f16(acc[mi][nj], al[mi], bhp);
                }
        }
        __syncthreads();
    }

    #pragma unroll
    for (int mi = 0; mi < 2; mi++) {
        const int rr = wm * 32 + mi * 16 + (lid >> 2);
        const float bv0 = __ldg(&bias[m0 + rr]);
        const float bv1 = __ldg(&bias[m0 + rr + 8]);
        float* y0 = Y + ((size_t)b * M + m0 + rr) * NPIX + p0 + wn * 32 + (lid & 3) * 2;
        float* y1 = y0 + 8 * NPIX;
        #pragma unroll
        for (int nj = 0; nj < 4; nj++) {
            *(float2*)(y0 + nj * 8) =
                make_float2(acc[mi][nj][0] + bv0, acc[mi][nj][1] + bv0);
            *(float2*)(y1 + nj * 8) =
                make_float2(acc[mi][nj][2] + bv1, acc[mi][nj][3] + bv1);
        }
    }
}

// ---------------------------------------------------------------------------
// Attention on tensor cores (fp16 2-term). CTA = (64-query tile, h, b),
// 256 threads, 8 warps: wn=wid&3 (16 queries), wm=wid>>2 (128 keys).
// Q split hi/lo; K, V single-rounded fp16. S and O in mma accumulators.
// Layouts: Qs[d][n] stride 144B; Ks/Vs[d][m] stride 528B.
// ---------------------------------------------------------------------------
#define AT_QH   0
#define AT_QL   9216
#define AT_KH   18432      // 64*528 = 33792
#define AT_VH   52224      // 64*528 = 33792
#define AT_REL  86016      // 961 floats
#define AT_MAXB 89872      // [2][64] float
#define AT_SUMB 90384      // [2][64] float
#define AT_RS   90896      // [64] float
#define AT_SMEM 91152
// O-partial overlay [2][64][68] fp32 (34816 B) at offset 0 (Q+K dead by then)

__global__ __launch_bounds__(256, 1) void attn_mma(const float* __restrict__ rel)
{
    extern __shared__ char sm[];
    float* smf = (float*)sm;
    const uint32_t sb = smem_to_u32(sm);

    const int tid  = threadIdx.x;
    const int lane = tid & 31;
    const int wid  = tid >> 5;
    const int wn   = wid & 3;
    const int wm   = wid >> 2;
    const int n0g  = blockIdx.x * 64;
    const int h    = blockIdx.y;
    const int b    = blockIdx.z;

    const float* qkv = g_qkv + (size_t)b * (3 * CH * NPIX);
    const float* qg = qkv + (h * HD) * NPIX;
    const float* kg = qkv + (CH + h * HD) * NPIX;
    const float* vg = qkv + (2 * CH + h * HD) * NPIX;

    // ---- convert Q (split), K and V (single) into smem ---------------------
    #pragma unroll
    for (int it = 0; it < 4; it++) {               // Q: 64d x 64n
        int i = tid + it * 256;
        int d = i >> 4, nq = (i & 15) * 4;
        float4 v = *(const float4*)&qg[d * NPIX + n0g + nq];
        split4_f16(sm + AT_QH + d * 144 + nq * 2, sm + AT_QL + d * 144 + nq * 2, v);
    }
    #pragma unroll
    for (int it = 0; it < 16; it++) {              // K: 64d x 256m
        int i = tid + it * 256;
        int d = i >> 6, mq = (i & 63) * 4;
        float4 v = *(const float4*)&kg[d * NPIX + mq];
        cvt4_f16(sm + AT_KH + d * 528 + mq * 2, v);
    }
    #pragma unroll
    for (int it = 0; it < 16; it++) {              // V: 64d x 256m
        int i = tid + it * 256;
        int d = i >> 6, mq = (i & 63) * 4;
        float4 v = *(const float4*)&vg[d * NPIX + mq];
        cvt4_f16(sm + AT_VH + d * 528 + mq * 2, v);
    }
    for (int i = tid; i < 961; i += 256)
        smf[AT_REL / 4 + i] = rel[h * 961 + i];
    __syncthreads();

    // ---- S = Q^T K (2-term split) ------------------------------------------
    float acc[16][4];
    #pragma unroll
    for (int f = 0; f < 16; f++)
        #pragma unroll
        for (int e = 0; e < 4; e++) acc[f][e] = 0.f;

    const uint32_t a_row = ((lane >> 4) & 1) * 8 + (lane & 7);
    const uint32_t a_col = (uint32_t)(wn * 16 + ((lane >> 3) & 1) * 8) * 2;
    const uint32_t b_row = ((lane >> 3) & 1) * 8 + (lane & 7);
    const uint32_t b_col8 = ((lane >> 4) & 1) * 8;

    #pragma unroll
    for (int s = 0; s < 4; s++) {
        uint32_t ah[4], al[4];
        ldm_x4_t(ah, sb + AT_QH + (s * 16 + a_row) * 144 + a_col);
        ldm_x4_t(al, sb + AT_QL + (s * 16 + a_row) * 144 + a_col);
        #pragma unroll
        for (int mg = 0; mg < 8; mg++) {
            const uint32_t mcol = (uint32_t)(wm * 128 + mg * 16 + b_col8) * 2;
            uint32_t bh[4];
            ldm_x4_t(bh, sb + AT_KH + (s * 16 + b_row) * 528 + mcol);
            mma_f16(acc[2 * mg], ah, &bh[0]);
            mma_f16(acc[2 * mg], al, &bh[0]);
            mma_f16(acc[2 * mg + 1], ah, &bh[2]);
            mma_f16(acc[2 * mg + 1], al, &bh[2]);
        }
    }

    // ---- scale + rel bias, row max -----------------------------------------
    const int rq  = lane >> 2;
    const int nr  = n0g + wn * 16 + rq;
    const int nr8 = nr + 8;
    const int nb0 = (nr >> 4) * 31 + (nr & 15) + 480;
    const int nb8 = (nr8 >> 4) * 31 + (nr8 & 15) + 480;
    const float* Rs = smf + AT_REL / 4;

    float mx0 = -1e30f, mx8 = -1e30f;
    #pragma unroll
    for (int f = 0; f < 16; f++) {
        int mc = wm * 128 + f * 8 + (lane & 3) * 2;
        int mi0 = (mc >> 4) * 31 + (mc & 15);
        int mi1 = ((mc + 1) >> 4) * 31 + ((mc + 1) & 15);
        acc[f][0] = fmaf(acc[f][0], 0.125f, Rs[nb0 - mi0]);
        acc[f][1] = fmaf(acc[f][1], 0.125f, Rs[nb0 - mi1]);
        acc[f][2] = fmaf(acc[f][2], 0.125f, Rs[nb8 - mi0]);
        acc[f][3] = fmaf(acc[f][3], 0.125f, Rs[nb8 - mi1]);
        mx0 = fmaxf(mx0, fmaxf(acc[f][0], acc[f][1]));
        mx8 = fmaxf(mx8, fmaxf(acc[f][2], acc[f][3]));
    }
    mx0 = fmaxf(mx0, __shfl_xor_sync(0xFFFFFFFF, mx0, 1));
    mx0 = fmaxf(mx0, __shfl_xor_sync(0xFFFFFFFF, mx0, 2));
    mx8 = fmaxf(mx8, __shfl_xor_sync(0xFFFFFFFF, mx8, 1));
    mx8 = fmaxf(mx8, __shfl_xor_sync(0xFFFFFFFF, mx8, 2));
    float* maxb = smf + AT_MAXB / 4;
    const int row = wn * 16 + rq;
    if ((lane & 3) == 0) {
        maxb[wm * 64 + row]     = mx0;
        maxb[wm * 64 + row + 8] = mx8;
    }
    __syncthreads();
    mx0 = fmaxf(maxb[row],     maxb[64 + row]);
    mx8 = fmaxf(maxb[row + 8], maxb[64 + row + 8]);

    // ---- exp + row sum -------------------------------------------------------
    float s0 = 0.f, s8 = 0.f;
    #pragma unroll
    for (int f = 0; f < 16; f++) {
        acc[f][0] = fast_exp(acc[f][0] - mx0);
        acc[f][1] = fast_exp(acc[f][1] - mx0);
        acc[f][2] = fast_exp(acc[f][2] - mx8);
        acc[f][3] = fast_exp(acc[f][3] - mx8);
        s0 += acc[f][0] + acc[f][1];
        s8 += acc[f][2] + acc[f][3];
    }
    s0 += __shfl_xor_sync(0xFFFFFFFF, s0, 1);
    s0 += __shfl_xor_sync(0xFFFFFFFF, s0, 2);
    s8 += __shfl_xor_sync(0xFFFFFFFF, s8, 1);
    s8 += __shfl_xor_sync(0xFFFFFFFF, s8, 2);
    float* sumb = smf + AT_SUMB / 4;
    if ((lane & 3) == 0) {
        sumb[wm * 64 + row]     = s0;
        sumb[wm * 64 + row + 8] = s8;
    }
    __syncthreads();
    if (wm == 0 && (lane & 3) == 0) {
        smf[AT_RS / 4 + row]     = 1.f / (sumb[row] + sumb[64 + row]);
        smf[AT_RS / 4 + row + 8] = 1.f / (sumb[row + 8] + sumb[64 + row + 8]);
    }

    // ---- repack P (unnormalized) into fp16 hi/lo A-fragments ----------------
    uint32_t ph[16][2], pl[16][2];
    #pragma unroll
    for (int f = 0; f < 16; f++) {
        __half2 h01 = __floats2half2_rn(acc[f][0], acc[f][1]);
        __half2 h23 = __floats2half2_rn(acc[f][2], acc[f][3]);
        float2 f01 = __half22float2(h01), f23 = __half22float2(h23);
        __half2 l01 = __floats2half2_rn(acc[f][0] - f01.x, acc[f][1] - f01.y);
        __half2 l23 = __floats2half2_rn(acc[f][2] - f23.x, acc[f][3] - f23.y);
        ph[f][0] = h2u(h01);
        ph[f][1] = h2u(h23);
        pl[f][0] = h2u(l01);
        pl[f][1] = h2u(l23);
    }

    // ---- O_partial = P V^T ----------------------------------------------------
    float oacc[8][4];
    #pragma unroll
    for (int g = 0; g < 8; g++)
        #pragma unroll
        for (int e = 0; e < 4; e++) oacc[g][e] = 0.f;

    const uint32_t v_row = ((lane >> 4) & 1) * 8 + (lane & 7);
    const uint32_t v_colh = ((lane >> 3) & 1) * 16;

    #pragma unroll
    for (int s = 0; s < 8; s++) {
        uint32_t a_h[4] = {ph[2 * s][0], ph[2 * s][1], ph[2 * s + 1][0], ph[2 * s + 1][1]};
        uint32_t a_l[4] = {pl[2 * s][0], pl[2 * s][1], pl[2 * s + 1][0], pl[2 * s + 1][1]};
        const uint32_t vcol = (uint32_t)(wm * 128 + s * 16) * 2 + v_colh;
        #pragma unroll
        for (int dg = 0; dg < 4; dg++) {
            uint32_t bh[4];
            const uint32_t vaddr = (dg * 16 + v_row) * 528 + vcol;
            ldm_x4(bh, sb + AT_VH + vaddr);
            mma_f16(oacc[2 * dg], a_h, &bh[0]);
            mma_f16(oacc[2 * dg], a_l, &bh[0]);
            mma_f16(oacc[2 * dg + 1], a_h, &bh[2]);
            mma_f16(oacc[2 * dg + 1], a_l, &bh[2]);
        }
    }

    // ---- cross-wm O reduce via smem (overlay on dead Q+K regions) -------------
    float* Osm = smf;                            // [2][64][68] floats, offset 0
    #pragma unroll
    for (int g = 0; g < 8; g++) {
        int d = g * 8 + (lane & 3) * 2;
        float* q0 = Osm + (wm * 64 + d) * 68 + row;
        float* q1 = Osm + (wm * 64 + d + 1) * 68 + row;
        q0[0] = oacc[g][0];
        q1[0] = oacc[g][1];
        q0[8] = oacc[g][2];
        q1[8] = oacc[g][3];
    }
    __syncthreads();

    // ---- final: sum halves, normalize, coalesced fp32 store -------------------
    {
        const int d  = tid >> 2;
        const int nq = (tid & 3) * 16;
        const float* rs = smf + AT_RS / 4;
        float* og = g_att + ((size_t)b * CH + h * HD + d) * NPIX + n0g;
        #pragma unroll
        for (int j = 0; j < 4; j++) {
            int n = nq + j * 4;
            float4 x0 = *(float4*)&Osm[d * 68 + n];
            float4 x1 = *(float4*)&Osm[(64 + d) * 68 + n];
            float4 r  = *(float4*)&rs[n];
            float4 o;
            o.x = (x0.x + x1.x) * r.x;
            o.y = (x0.y + x1.y) * r.y;
            o.z = (x0.z + x1.z) * r.z;
            o.w = (x0.w + x1.w) * r.w;
            *(float4*)&og[n] = o;
        }
    }
}

// ---------------------------------------------------------------------------
extern "C" void kernel_launch(void* const* d_in, const int* in_sizes, int n_in,
                              void* d_out, int out_size)
{
    const float* x      = (const float*)d_in[0];
    const float* qkv_w  = (const float*)d_in[1];
    const float* qkv_b  = (const float*)d_in[2];
    const float* out_w  = (const float*)d_in[3];
    const float* out_b  = (const float*)d_in[4];
    const float* rel    = (const float*)d_in[5];
    float* out = (float*)d_out;

    void* p_qkv = nullptr;
    void* p_att = nullptr;
    cudaGetSymbolAddress(&p_qkv, g_qkv);
    cudaGetSymbolAddress(&p_att, g_att);

    cudaFuncSetAttribute(attn_mma,
                         cudaFuncAttributeMaxDynamicSharedMemorySize, AT_SMEM);

    // 1) QKV projection (fp16 2-term)
    gemm_mma<3 * CH><<<dim3(NPIX / 64, (3 * CH) / 64, BATCH), 128>>>(
        qkv_w, x, qkv_b, (float*)p_qkv);

    // 2) Attention (tensor cores, fp16 2-term)
    attn_mma<<<dim3(NPIX / 64, HEADS, BATCH), 256, AT_SMEM>>>(rel);

    // 3) Output projection
    gemm_mma<CH><<<dim3(NPIX / 64, CH / 64, BATCH), 128>>>(
        out_w, (const float*)p_att, out_b, out);
}